// round 1
// baseline (speedup 1.0000x reference)
#include <cuda_runtime.h>
#include <cstdint>

#define BN 2048   // B*N rows
#define NN 256    // N (neighbors)
#define D  128
#define E  64

// Scratch (device globals: allocation-free rule)
__device__ float g_hW1[BN * E];
__device__ float g_aggmean[BN * D];
__device__ float g_aggmax[BN * D];

__device__ __forceinline__ uint32_t f2tf32(float f) {
    uint32_t r;
    asm("cvt.rna.tf32.f32 %0, %1;" : "=r"(r) : "f"(f));
    return r;
}

// ---------------------------------------------------------------------------
// K1: hW1[b,i,e] = h[b,i,:] @ W1[0:128,e] + b1[e]    (2048 x 64)
// ---------------------------------------------------------------------------
__global__ void __launch_bounds__(64) k1_hW1(const float* __restrict__ h,
                                             const float* __restrict__ W1,
                                             const float* __restrict__ b1) {
    __shared__ float sh[D];
    const int bi = blockIdx.x;
    const int tid = threadIdx.x;  // 64
    sh[tid]      = h[bi * D + tid];
    sh[tid + 64] = h[bi * D + tid + 64];
    __syncthreads();
    float acc = b1[tid];
#pragma unroll 8
    for (int d = 0; d < D; d++) acc += sh[d] * W1[d * E + tid];
    g_hW1[bi * E + tid] = acc;
}

// ---------------------------------------------------------------------------
// K2: per (b,i): compact active j, R = relu(hW1 + ef@W1e) [tf32],
//     logits = R @ W2 via mma.sync tf32, gate = sigmoid, fused masked
//     sum/max/min over j  ->  agg_mean, agg_max
// SMEM (floats): sW2 64*136 | sR 64*68 | hW1 64 | W1e 192 | b2 128 | h 128
//                redS/Mx/Mn 3*256 | jidx 256(int) | misc 8(int)
// ---------------------------------------------------------------------------
#define K2_SMEM_BYTES ((14336 + 264) * 4)

__global__ void __launch_bounds__(256) k2_main(
    const float* __restrict__ h, const float* __restrict__ ef,
    const unsigned char* __restrict__ adj,
    const float* __restrict__ W1, const float* __restrict__ W2,
    const float* __restrict__ b2) {
    extern __shared__ float sm[];
    float* sW2    = sm;            // 64*136 tf32-rounded
    float* sR     = sm + 8704;     // 64*68  tf32-rounded
    float* s_hW1  = sm + 13056;    // 64
    float* sW1e   = sm + 13120;    // 3*64
    float* s_b2   = sm + 13312;    // 128
    float* s_h    = sm + 13440;    // 128
    float* s_redS = sm + 13568;    // 2*128
    float* s_redMx= sm + 13824;    // 2*128
    float* s_redMn= sm + 14080;    // 2*128
    int*   s_jidx = (int*)(sm + 14336);  // 256
    int*   s_misc = s_jidx + 256;        // 8 (per-warp popcounts)

    const int bi   = blockIdx.x;
    const int tid  = threadIdx.x;
    const int lane = tid & 31;
    const int warp = tid >> 5;
    const int gid  = lane >> 2;   // 0..7
    const int tg   = lane & 3;    // 0..3
    const int wm   = warp & 1;    // M-group (rows)
    const int wn   = warp >> 1;   // N-group (cols)

    // Stage weights/rows into SMEM (W2 converted to tf32 once per CTA)
    for (int idx = tid; idx < E * D; idx += 256) {
        int e = idx >> 7, d = idx & 127;
        sW2[e * 136 + d] = __uint_as_float(f2tf32(W2[idx]));
    }
    if (tid < E) s_hW1[tid] = g_hW1[bi * E + tid];
    for (int idx = tid; idx < 3 * E; idx += 256) sW1e[idx] = W1[D * E + idx];
    if (tid < D) { s_b2[tid] = b2[tid]; s_h[tid] = h[bi * D + tid]; }

    // Deterministic compaction of active j (ballot + scan)
    const unsigned char mraw = adj[(size_t)bi * NN + tid];
    const bool m = (mraw != 0);
    unsigned bal = __ballot_sync(0xffffffffu, m);
    if (lane == 0) s_misc[warp] = __popc(bal);
    __syncthreads();
    int base = 0, cnt = 0;
#pragma unroll
    for (int w = 0; w < 8; w++) {
        int c = s_misc[w];
        if (w < warp) base += c;
        cnt += c;
    }
    if (m) s_jidx[base + __popc(bal & ((1u << lane) - 1u))] = tid;
    __syncthreads();

    float S[8], Mx[8], Mn[8];
#pragma unroll
    for (int i = 0; i < 8; i++) { S[i] = 0.f; Mx[i] = -1e30f; Mn[i] = 1e30f; }

    const int nTiles = (cnt + 63) >> 6;
    const int rrow = tid >> 2;          // 0..63  (R build row)
    const int re0  = (tid & 3) << 4;    // e-chunk base

    for (int t = 0; t < nTiles; t++) {
        __syncthreads();  // protect sR reuse across tiles
        // ---- Build R tile (64 rows x 64 e), tf32-rounded ----
        float f0 = 0.f, f1 = 0.f, f2v = 0.f;
        const int jg = t * 64 + rrow;
        if (jg < cnt) {
            const float* p = ef + ((size_t)bi * NN + s_jidx[jg]) * 3;
            f0 = p[0]; f1 = p[1]; f2v = p[2];
        }
#pragma unroll
        for (int i = 0; i < 16; i++) {
            int e = re0 + i;
            float pre = s_hW1[e] + f0 * sW1e[e] + f1 * sW1e[64 + e] + f2v * sW1e[128 + e];
            pre = fmaxf(pre, 0.f);
            sR[rrow * 68 + e] = __uint_as_float(f2tf32(pre));
        }
        __syncthreads();

        // ---- 64x128 logits tile: warp = 32 rows x 32 cols (2 mt x 4 nt), K=64 ----
        float c[2][4][4];
#pragma unroll
        for (int mt = 0; mt < 2; mt++)
#pragma unroll
            for (int nt = 0; nt < 4; nt++)
#pragma unroll
                for (int q = 0; q < 4; q++) c[mt][nt][q] = 0.f;

#pragma unroll
        for (int kc = 0; kc < 8; kc++) {
            const int k = kc * 8;
            uint32_t a[2][4], b[4][2];
#pragma unroll
            for (int mt = 0; mt < 2; mt++) {
                const int row = wm * 32 + mt * 16 + gid;
                const float* pr = sR + row * 68 + k + tg;
                a[mt][0] = __float_as_uint(pr[0]);
                a[mt][1] = __float_as_uint(pr[8 * 68]);
                a[mt][2] = __float_as_uint(pr[4]);
                a[mt][3] = __float_as_uint(pr[8 * 68 + 4]);
            }
#pragma unroll
            for (int nt = 0; nt < 4; nt++) {
                const int col = wn * 32 + nt * 8 + gid;
                const float* pb = sW2 + (k + tg) * 136 + col;
                b[nt][0] = __float_as_uint(pb[0]);
                b[nt][1] = __float_as_uint(pb[4 * 136]);
            }
#pragma unroll
            for (int mt = 0; mt < 2; mt++)
#pragma unroll
                for (int nt = 0; nt < 4; nt++) {
                    asm("mma.sync.aligned.m16n8k8.row.col.f32.tf32.tf32.f32 "
                        "{%0,%1,%2,%3}, {%4,%5,%6,%7}, {%8,%9}, {%0,%1,%2,%3};\n"
                        : "+f"(c[mt][nt][0]), "+f"(c[mt][nt][1]),
                          "+f"(c[mt][nt][2]), "+f"(c[mt][nt][3])
                        : "r"(a[mt][0]), "r"(a[mt][1]), "r"(a[mt][2]), "r"(a[mt][3]),
                          "r"(b[nt][0]), "r"(b[nt][1]));
                }
        }

        // ---- Epilogue: bias + sigmoid + masked sum/max/min ----
#pragma unroll
        for (int mt = 0; mt < 2; mt++)
#pragma unroll
            for (int q = 0; q < 4; q++) {
                const int rloc = wm * 32 + mt * 16 + gid + ((q >> 1) << 3);
                const bool v = (t * 64 + rloc) < cnt;
#pragma unroll
                for (int nt = 0; nt < 4; nt++) {
                    const int d = wn * 32 + nt * 8 + 2 * tg + (q & 1);
                    const float logit = c[mt][nt][q] + s_b2[d];
                    const float g = __fdividef(1.f, 1.f + __expf(-logit));
                    if (v) {
                        const int si = nt * 2 + (q & 1);
                        S[si] += g;
                        Mx[si] = fmaxf(Mx[si], g);
                        Mn[si] = fminf(Mn[si], g);
                    }
                }
            }
    }

    // ---- Reduce across the 8 lanes sharing each d (bits 2..4 of lane) ----
#pragma unroll
    for (int i = 0; i < 8; i++) {
#pragma unroll
        for (int off = 4; off < 32; off <<= 1) {
            S[i]  += __shfl_xor_sync(0xffffffffu, S[i], off);
            Mx[i]  = fmaxf(Mx[i], __shfl_xor_sync(0xffffffffu, Mx[i], off));
            Mn[i]  = fminf(Mn[i], __shfl_xor_sync(0xffffffffu, Mn[i], off));
        }
    }
    if (lane < 4) {
#pragma unroll
        for (int nt = 0; nt < 4; nt++)
#pragma unroll
            for (int q = 0; q < 2; q++) {
                const int d = wn * 32 + nt * 8 + 2 * lane + q;
                const int si = nt * 2 + q;
                s_redS [wm * 128 + d] = S[si];
                s_redMx[wm * 128 + d] = Mx[si];
                s_redMn[wm * 128 + d] = Mn[si];
            }
    }
    __syncthreads();
    if (tid < D) {
        const float St  = s_redS[tid]  + s_redS[128 + tid];
        const float Mxt = fmaxf(s_redMx[tid], s_redMx[128 + tid]);
        const float Mnt = fminf(s_redMn[tid], s_redMn[128 + tid]);
        const float hv  = s_h[tid];
        const float cl  = (cnt > 0) ? (float)cnt : 1.f;
        g_aggmean[bi * D + tid] = St * hv / cl;
        float amax = 0.f;
        if (cnt > 0) amax = (hv >= 0.f) ? hv * Mxt : hv * Mnt;
        g_aggmax[bi * D + tid] = amax;
    }
}

// ---------------------------------------------------------------------------
// K3: upd = relu([h, agg_mean, agg_max] @ U1 + b3) @ U2 + b4
//     out = LayerNorm(h + upd) * gamma + beta          (16 rows / CTA)
// ---------------------------------------------------------------------------
#define TR 16
__global__ void __launch_bounds__(256) k3_upd(
    const float* __restrict__ h,
    const float* __restrict__ U1, const float* __restrict__ b3,
    const float* __restrict__ U2, const float* __restrict__ b4,
    const float* __restrict__ gamma, const float* __restrict__ beta,
    float* __restrict__ out) {
    __shared__ float s_in[TR][384];
    __shared__ float s_mid[TR][129];
    __shared__ float s_x[TR][129];
    const int tid = threadIdx.x;
    const int r0 = blockIdx.x * TR;

    for (int idx = tid; idx < TR * D; idx += 256) {
        const int r = idx >> 7, d = idx & 127;
        s_in[r][d]       = h[(size_t)(r0 + r) * D + d];
        s_in[r][128 + d] = g_aggmean[(size_t)(r0 + r) * D + d];
        s_in[r][256 + d] = g_aggmax[(size_t)(r0 + r) * D + d];
    }
    __syncthreads();

    const int e  = tid & 127;
    const int rb = (tid >> 7) * 8;
    float acc[8];
#pragma unroll
    for (int r = 0; r < 8; r++) acc[r] = 0.f;
    for (int k = 0; k < 384; k++) {
        const float w = U1[k * D + e];
#pragma unroll
        for (int r = 0; r < 8; r++) acc[r] += s_in[rb + r][k] * w;
    }
    const float bb = b3[e];
#pragma unroll
    for (int r = 0; r < 8; r++) s_mid[rb + r][e] = fmaxf(acc[r] + bb, 0.f);
    __syncthreads();

#pragma unroll
    for (int r = 0; r < 8; r++) acc[r] = 0.f;
    for (int k = 0; k < D; k++) {
        const float w = U2[k * D + e];
#pragma unroll
        for (int r = 0; r < 8; r++) acc[r] += s_mid[rb + r][k] * w;
    }
    const float b4v = b4[e];
#pragma unroll
    for (int r = 0; r < 8; r++) s_x[rb + r][e] = s_in[rb + r][e] + acc[r] + b4v;
    __syncthreads();

    // LayerNorm: 8 warps, 2 rows each
    const int warp = tid >> 5, lane = tid & 31;
#pragma unroll
    for (int rr = 0; rr < 2; rr++) {
        const int r = warp * 2 + rr;
        float s = 0.f, s2 = 0.f, v[4];
#pragma unroll
        for (int i = 0; i < 4; i++) {
            v[i] = s_x[r][lane + i * 32];
            s += v[i]; s2 += v[i] * v[i];
        }
#pragma unroll
        for (int off = 1; off < 32; off <<= 1) {
            s  += __shfl_xor_sync(0xffffffffu, s, off);
            s2 += __shfl_xor_sync(0xffffffffu, s2, off);
        }
        const float mu  = s * (1.f / 128.f);
        const float var = s2 * (1.f / 128.f) - mu * mu;
        const float inv = rsqrtf(var + 1e-5f);
#pragma unroll
        for (int i = 0; i < 4; i++) {
            const int d = lane + i * 32;
            out[(size_t)(r0 + r) * D + d] = (v[i] - mu) * inv * gamma[d] + beta[d];
        }
    }
}

// ---------------------------------------------------------------------------
extern "C" void kernel_launch(void* const* d_in, const int* in_sizes, int n_in,
                              void* d_out, int out_size) {
    const float* h    = (const float*)d_in[0];
    const float* ef   = (const float*)d_in[1];
    const unsigned char* adj = (const unsigned char*)d_in[2];
    const float* W1   = (const float*)d_in[3];
    const float* b1   = (const float*)d_in[4];
    const float* W2   = (const float*)d_in[5];
    const float* b2   = (const float*)d_in[6];
    const float* U1   = (const float*)d_in[7];
    const float* b3   = (const float*)d_in[8];
    const float* U2   = (const float*)d_in[9];
    const float* b4   = (const float*)d_in[10];
    const float* gamma= (const float*)d_in[11];
    const float* beta = (const float*)d_in[12];
    float* out = (float*)d_out;

    cudaFuncSetAttribute(k2_main, cudaFuncAttributeMaxDynamicSharedMemorySize,
                         K2_SMEM_BYTES);

    k1_hW1<<<BN, 64>>>(h, W1, b1);
    k2_main<<<BN, 256, K2_SMEM_BYTES>>>(h, ef, adj, W1, W2, b2);
    k3_upd<<<BN / TR, 256>>>(h, U1, b3, U2, b4, gamma, beta, out);
}

// round 2
// speedup vs baseline: 1.0613x; 1.0613x over previous
#include <cuda_runtime.h>
#include <cuda_bf16.h>
#include <cstdint>

#define BN 2048   // B*N rows
#define NN 256    // N (neighbors)
#define D  128
#define E  64

// Scratch (device globals: allocation-free rule)
__device__ __align__(16) float g_aggmean[BN * D];
__device__ __align__(16) float g_aggmax[BN * D];

__device__ __forceinline__ float tanh_fast(float x) {
    float y;
    asm("tanh.approx.f32 %0, %1;" : "=f"(y) : "f"(x));
    return y;
}

__device__ __forceinline__ uint32_t pack_bf2(__nv_bfloat16 a, __nv_bfloat16 b) {
    __nv_bfloat162 v = __halves2bfloat162(a, b);  // a = low half = even index
    uint32_t r;
    memcpy(&r, &v, 4);
    return r;
}

#define MMA_BF16(C, A, B)                                                    \
    asm("mma.sync.aligned.m16n8k16.row.col.f32.bf16.bf16.f32 "               \
        "{%0,%1,%2,%3}, {%4,%5,%6,%7}, {%8,%9}, {%0,%1,%2,%3};\n"            \
        : "+f"((C)[0]), "+f"((C)[1]), "+f"((C)[2]), "+f"((C)[3])             \
        : "r"((A)[0]), "r"((A)[1]), "r"((A)[2]), "r"((A)[3]),                \
          "r"((B)[0]), "r"((B)[1]))

// ---------------------------------------------------------------------------
// K2: per (b,i): hW1 prologue (folded old k1), compact active j,
//     R = relu(hW1 + ef@W1e) split to bf16 hi/lo,
//     logits = R @ W2 via 3-term bf16 mma.sync (near-fp32 accuracy),
//     gate = sigmoid(tanh form), fused masked sum/max/min over j.
//     Each CTA handles 2 consecutive (b,i) rows (weights staged once).
// ---------------------------------------------------------------------------
// SMEM word offsets:
//  sW2hi 0..4351 (32x136 u32), sW2lo 4352..8703, sRhi 8704..11007 (64x36),
//  sRlo 11008..13311, s_hW1 13312(64), sW1e 13376(192), s_b2 13568(128),
//  s_h 13696(128), s_redS 13824(256, alias s_part), s_redMx 14080(256),
//  s_redMn 14336(256), s_jidx 14592(256 int), s_misc 14848(8 int)
#define K2_SMEM_BYTES (14856 * 4)

__global__ void __launch_bounds__(256) k2_main(
    const float* __restrict__ h, const float* __restrict__ ef,
    const unsigned char* __restrict__ adj,
    const float* __restrict__ W1, const float* __restrict__ b1,
    const float* __restrict__ W2, const float* __restrict__ b2) {
    extern __shared__ float sm[];
    uint32_t* sW2hi = (uint32_t*)sm;
    uint32_t* sW2lo = (uint32_t*)(sm + 4352);
    uint32_t* sRhi  = (uint32_t*)(sm + 8704);
    uint32_t* sRlo  = (uint32_t*)(sm + 11008);
    float* s_hW1  = sm + 13312;
    float* sW1e   = sm + 13376;
    float* s_b2   = sm + 13568;
    float* s_h    = sm + 13696;
    float* s_redS = sm + 13824;
    float* s_part = s_redS;           // alias (disjoint lifetimes, synced)
    float* s_redMx= sm + 14080;
    float* s_redMn= sm + 14336;
    int*   s_jidx = (int*)(sm + 14592);
    int*   s_misc = s_jidx + 256;

    const int tid  = threadIdx.x;
    const int lane = tid & 31;
    const int warp = tid >> 5;
    const int gid  = lane >> 2;   // 0..7
    const int tg   = lane & 3;    // 0..3
    const int wm   = warp & 1;    // M-group (rows)
    const int wn   = warp >> 1;   // N-group (cols)

    // ---- Stage shared weights once per CTA (bf16 hi/lo split of W2) ----
    for (int idx = tid; idx < E * D; idx += 256) {
        const int e = idx >> 7, d = idx & 127;
        const float w = W2[idx];
        const __nv_bfloat16 hi = __float2bfloat16(w);
        const __nv_bfloat16 lo = __float2bfloat16(w - __bfloat162float(hi));
        ((__nv_bfloat16*)sW2hi)[((e >> 1) * 136 + d) * 2 + (e & 1)] = hi;
        ((__nv_bfloat16*)sW2lo)[((e >> 1) * 136 + d) * 2 + (e & 1)] = lo;
    }
    for (int idx = tid; idx < 3 * E; idx += 256) sW1e[idx] = W1[D * E + idx];
    if (tid < D) s_b2[tid] = b2[tid];

    for (int sub = 0; sub < 2; sub++) {
        const int bi = blockIdx.x * 2 + sub;
        __syncthreads();   // protects s_h/s_jidx/s_part reuse across subs + weight staging

        if (tid < D) s_h[tid] = h[bi * D + tid];

        // Deterministic compaction of active j (ballot + scan)
        const bool m = adj[(size_t)bi * NN + tid] != 0;
        const unsigned bal = __ballot_sync(0xffffffffu, m);
        if (lane == 0) s_misc[warp] = __popc(bal);
        __syncthreads();
        int base = 0, cnt = 0;
#pragma unroll
        for (int w = 0; w < 8; w++) {
            const int c = s_misc[w];
            if (w < warp) base += c;
            cnt += c;
        }
        if (m) s_jidx[base + __popc(bal & ((1u << lane) - 1u))] = tid;

        // hW1 prologue (folded k1): 4-way K-split partial sums
        {
            const int e = tid & 63, q = tid >> 6;
            float acc = 0.f;
            const float* wp = W1 + (q * 32) * E + e;
            const float* hp = s_h + q * 32;
#pragma unroll 8
            for (int k = 0; k < 32; k++) acc += hp[k] * wp[k * E];
            s_part[q * 64 + e] = acc;
        }
        __syncthreads();
        if (tid < E)
            s_hW1[tid] = b1[tid] + s_part[tid] + s_part[64 + tid] +
                         s_part[128 + tid] + s_part[192 + tid];
        __syncthreads();

        float S[8], Mx[8], Mn[8];
#pragma unroll
        for (int i = 0; i < 8; i++) { S[i] = 0.f; Mx[i] = -1e30f; Mn[i] = 1e30f; }

        const int nTiles = (cnt + 63) >> 6;
        const int rrow = tid >> 2;          // 0..63 (R build row)
        const int ep   = (tid & 3) * 8;     // bf16x2-pair chunk base

        for (int t = 0; t < nTiles; t++) {
            if (t) __syncthreads();   // sR reuse across tiles
            // ---- Build R tile (64 rows x 64 e), bf16 hi/lo split ----
            float f0 = 0.f, f1 = 0.f, f2v = 0.f;
            const int jg = t * 64 + rrow;
            if (jg < cnt) {
                const float* p = ef + ((size_t)bi * NN + s_jidx[jg]) * 3;
                f0 = p[0]; f1 = p[1]; f2v = p[2];
            }
#pragma unroll
            for (int pidx = 0; pidx < 8; pidx++) {
                const int e0 = (ep + pidx) * 2;
                float pa = s_hW1[e0]     + f0 * sW1e[e0]     + f1 * sW1e[64 + e0]     + f2v * sW1e[128 + e0];
                float pb = s_hW1[e0 + 1] + f0 * sW1e[e0 + 1] + f1 * sW1e[64 + e0 + 1] + f2v * sW1e[128 + e0 + 1];
                pa = fmaxf(pa, 0.f); pb = fmaxf(pb, 0.f);
                const __nv_bfloat16 ha = __float2bfloat16(pa);
                const __nv_bfloat16 hb = __float2bfloat16(pb);
                const __nv_bfloat16 la = __float2bfloat16(pa - __bfloat162float(ha));
                const __nv_bfloat16 lb = __float2bfloat16(pb - __bfloat162float(hb));
                sRhi[rrow * 36 + ep + pidx] = pack_bf2(ha, hb);
                sRlo[rrow * 36 + ep + pidx] = pack_bf2(la, lb);
            }
            __syncthreads();

            // ---- 64x128 logits tile: warp = 32 rows x 32 cols, K=64 (4 x k16) ----
            float c[2][4][4];
#pragma unroll
            for (int mt = 0; mt < 2; mt++)
#pragma unroll
                for (int nt = 0; nt < 4; nt++)
#pragma unroll
                    for (int q = 0; q < 4; q++) c[mt][nt][q] = 0.f;

#pragma unroll
            for (int kc = 0; kc < 4; kc++) {
                uint32_t ah[2][4], al[2][4], bh[4][2], bl[4][2];
#pragma unroll
                for (int mt = 0; mt < 2; mt++) {
                    const int r = wm * 32 + mt * 16 + gid;
                    const int o1 = r * 36 + kc * 8 + tg;
                    const int o2 = (r + 8) * 36 + kc * 8 + tg;
                    ah[mt][0] = sRhi[o1];     ah[mt][1] = sRhi[o2];
                    ah[mt][2] = sRhi[o1 + 4]; ah[mt][3] = sRhi[o2 + 4];
                    al[mt][0] = sRlo[o1];     al[mt][1] = sRlo[o2];
                    al[mt][2] = sRlo[o1 + 4]; al[mt][3] = sRlo[o2 + 4];
                }
#pragma unroll
                for (int nt = 0; nt < 4; nt++) {
                    const int col = wn * 32 + nt * 8 + gid;
                    const int o1 = (kc * 8 + tg) * 136 + col;
                    const int o2 = (kc * 8 + 4 + tg) * 136 + col;
                    bh[nt][0] = sW2hi[o1]; bh[nt][1] = sW2hi[o2];
                    bl[nt][0] = sW2lo[o1]; bl[nt][1] = sW2lo[o2];
                }
#pragma unroll
                for (int mt = 0; mt < 2; mt++)
#pragma unroll
                    for (int nt = 0; nt < 4; nt++) {
                        MMA_BF16(c[mt][nt], ah[mt], bh[nt]);
                        MMA_BF16(c[mt][nt], al[mt], bh[nt]);
                        MMA_BF16(c[mt][nt], ah[mt], bl[nt]);
                    }
            }

            // ---- Epilogue: bias + sigmoid(tanh) + masked sum/max/min ----
#pragma unroll
            for (int mt = 0; mt < 2; mt++)
#pragma unroll
                for (int q = 0; q < 4; q++) {
                    const int rloc = wm * 32 + mt * 16 + gid + ((q >> 1) << 3);
                    const bool v = (t * 64 + rloc) < cnt;
#pragma unroll
                    for (int nt = 0; nt < 4; nt++) {
                        const int d = wn * 32 + nt * 8 + 2 * tg + (q & 1);
                        const float logit = c[mt][nt][q] + s_b2[d];
                        const float g = fmaf(0.5f, tanh_fast(0.5f * logit), 0.5f);
                        if (v) {
                            const int si = nt * 2 + (q & 1);
                            S[si] += g;
                            Mx[si] = fmaxf(Mx[si], g);
                            Mn[si] = fminf(Mn[si], g);
                        }
                    }
                }
        }

        // ---- Reduce across the 8 lanes sharing each d ----
#pragma unroll
        for (int i = 0; i < 8; i++) {
#pragma unroll
            for (int off = 4; off < 32; off <<= 1) {
                S[i]  += __shfl_xor_sync(0xffffffffu, S[i], off);
                Mx[i]  = fmaxf(Mx[i], __shfl_xor_sync(0xffffffffu, Mx[i], off));
                Mn[i]  = fminf(Mn[i], __shfl_xor_sync(0xffffffffu, Mn[i], off));
            }
        }
        __syncthreads();   // s_redS aliases s_part: ensure hW1 reads done (they are) + prior sub
        if (lane < 4) {
#pragma unroll
            for (int nt = 0; nt < 4; nt++)
#pragma unroll
                for (int q = 0; q < 2; q++) {
                    const int d = wn * 32 + nt * 8 + 2 * lane + q;
                    const int si = nt * 2 + q;
                    s_redS [wm * 128 + d] = S[si];
                    s_redMx[wm * 128 + d] = Mx[si];
                    s_redMn[wm * 128 + d] = Mn[si];
                }
        }
        __syncthreads();
        if (tid < D) {
            const float St  = s_redS[tid]  + s_redS[128 + tid];
            const float Mxt = fmaxf(s_redMx[tid], s_redMx[128 + tid]);
            const float Mnt = fminf(s_redMn[tid], s_redMn[128 + tid]);
            const float hv  = s_h[tid];
            const float cl  = (cnt > 0) ? (float)cnt : 1.f;
            g_aggmean[bi * D + tid] = St * hv / cl;
            float amax = 0.f;
            if (cnt > 0) amax = (hv >= 0.f) ? hv * Mxt : hv * Mnt;
            g_aggmax[bi * D + tid] = amax;
        }
    }
}

// ---------------------------------------------------------------------------
// K3: upd = relu([h, agg_mean, agg_max] @ U1 + b3) @ U2 + b4
//     out = LayerNorm(h + upd) * gamma + beta          (16 rows / CTA)
// ---------------------------------------------------------------------------
#define TR 16
__global__ void __launch_bounds__(256) k3_upd(
    const float* __restrict__ h,
    const float* __restrict__ U1, const float* __restrict__ b3,
    const float* __restrict__ U2, const float* __restrict__ b4,
    const float* __restrict__ gamma, const float* __restrict__ beta,
    float* __restrict__ out) {
    __shared__ __align__(16) float s_in[TR][384];
    __shared__ __align__(16) float s_mid[TR][132];
    __shared__ float s_x[TR][129];
    const int tid = threadIdx.x;
    const int r0 = blockIdx.x * TR;

    // Vectorized staging
    for (int idx = tid; idx < TR * 32; idx += 256) {
        const int r = idx >> 5, c = idx & 31;
        ((float4*)&s_in[r][0])[c]   = ((const float4*)(h + (size_t)(r0 + r) * D))[c];
        ((float4*)&s_in[r][128])[c] = ((const float4*)(g_aggmean + (size_t)(r0 + r) * D))[c];
        ((float4*)&s_in[r][256])[c] = ((const float4*)(g_aggmax + (size_t)(r0 + r) * D))[c];
    }
    __syncthreads();

    const int e  = tid & 127;
    const int rb = (tid >> 7) * 8;
    float acc[8];
#pragma unroll
    for (int r = 0; r < 8; r++) acc[r] = 0.f;
    for (int k = 0; k < 384; k += 4) {
        const float w0 = U1[(k + 0) * D + e];
        const float w1 = U1[(k + 1) * D + e];
        const float w2 = U1[(k + 2) * D + e];
        const float w3 = U1[(k + 3) * D + e];
#pragma unroll
        for (int r = 0; r < 8; r++) {
            const float4 v = *(const float4*)&s_in[rb + r][k];
            acc[r] += v.x * w0 + v.y * w1 + v.z * w2 + v.w * w3;
        }
    }
    const float bb = b3[e];
#pragma unroll
    for (int r = 0; r < 8; r++) s_mid[rb + r][e] = fmaxf(acc[r] + bb, 0.f);
    __syncthreads();

#pragma unroll
    for (int r = 0; r < 8; r++) acc[r] = 0.f;
    for (int k = 0; k < D; k += 4) {
        const float w0 = U2[(k + 0) * D + e];
        const float w1 = U2[(k + 1) * D + e];
        const float w2 = U2[(k + 2) * D + e];
        const float w3 = U2[(k + 3) * D + e];
#pragma unroll
        for (int r = 0; r < 8; r++) {
            const float4 v = *(const float4*)&s_mid[rb + r][k];
            acc[r] += v.x * w0 + v.y * w1 + v.z * w2 + v.w * w3;
        }
    }
    const float b4v = b4[e];
#pragma unroll
    for (int r = 0; r < 8; r++) s_x[rb + r][e] = s_in[rb + r][e] + acc[r] + b4v;
    __syncthreads();

    // LayerNorm: 8 warps, 2 rows each
    const int warp = tid >> 5, lane = tid & 31;
#pragma unroll
    for (int rr = 0; rr < 2; rr++) {
        const int r = warp * 2 + rr;
        float s = 0.f, s2 = 0.f, v[4];
#pragma unroll
        for (int i = 0; i < 4; i++) {
            v[i] = s_x[r][lane + i * 32];
            s += v[i]; s2 += v[i] * v[i];
        }
#pragma unroll
        for (int off = 1; off < 32; off <<= 1) {
            s  += __shfl_xor_sync(0xffffffffu, s, off);
            s2 += __shfl_xor_sync(0xffffffffu, s2, off);
        }
        const float mu  = s * (1.f / 128.f);
        const float var = s2 * (1.f / 128.f) - mu * mu;
        const float inv = rsqrtf(var + 1e-5f);
#pragma unroll
        for (int i = 0; i < 4; i++) {
            const int d = lane + i * 32;
            out[(size_t)(r0 + r) * D + d] = (v[i] - mu) * inv * gamma[d] + beta[d];
        }
    }
}

// ---------------------------------------------------------------------------
extern "C" void kernel_launch(void* const* d_in, const int* in_sizes, int n_in,
                              void* d_out, int out_size) {
    const float* h    = (const float*)d_in[0];
    const float* ef   = (const float*)d_in[1];
    const unsigned char* adj = (const unsigned char*)d_in[2];
    const float* W1   = (const float*)d_in[3];
    const float* b1   = (const float*)d_in[4];
    const float* W2   = (const float*)d_in[5];
    const float* b2   = (const float*)d_in[6];
    const float* U1   = (const float*)d_in[7];
    const float* b3   = (const float*)d_in[8];
    const float* U2   = (const float*)d_in[9];
    const float* b4   = (const float*)d_in[10];
    const float* gamma= (const float*)d_in[11];
    const float* beta = (const float*)d_in[12];
    float* out = (float*)d_out;

    cudaFuncSetAttribute(k2_main, cudaFuncAttributeMaxDynamicSharedMemorySize,
                         K2_SMEM_BYTES);

    k2_main<<<BN / 2, 256, K2_SMEM_BYTES>>>(h, ef, adj, W1, b1, W2, b2);
    k3_upd<<<BN / TR, 256>>>(h, U1, b3, U2, b4, gamma, beta, out);
}

// round 3
// speedup vs baseline: 1.2806x; 1.2066x over previous
#include <cuda_runtime.h>
#include <cuda_bf16.h>
#include <cstdint>

#define BN 2048   // B*N rows
#define NN 256    // N (neighbors)
#define D  128
#define E  64

// Scratch (device globals: allocation-free rule)
__device__ __align__(16) float g_aggmean[BN * D];
__device__ __align__(16) float g_aggmax[BN * D];

__device__ __forceinline__ float tanh_fast(float x) {
    float y;
    asm("tanh.approx.f32 %0, %1;" : "=f"(y) : "f"(x));
    return y;
}

__device__ __forceinline__ uint32_t f2tf32(float f) {
    uint32_t r;
    asm("cvt.rna.tf32.f32 %0, %1;" : "=r"(r) : "f"(f));
    return r;
}

// ---------------------------------------------------------------------------
// K2: per (b,i): hW1 prologue (folded k1), compact active j,
//     R = relu(hW1 + ef@W1e) [tf32], logits = R @ W2 via tf32 mma.sync,
//     gate = sigmoid(tanh form), fused masked sum/max/min over j.
//     Each CTA handles 2 consecutive (b,i) rows (weights staged once).
// ---------------------------------------------------------------------------
// SMEM word offsets:
//  sW2 0..8703 (64x136), sR 8704..13055 (64x68), s_hW1 13056(64),
//  sW1e 13120(192), s_b2 13312(128), s_h 13440(128),
//  s_redS 13568(256, alias s_part), s_redMx 13824(256), s_redMn 14080(256),
//  s_jidx 14336(256 int), s_misc 14592(8 int)
#define K2_SMEM_BYTES (14600 * 4)

__global__ void __launch_bounds__(256) k2_main(
    const float* __restrict__ h, const float* __restrict__ ef,
    const unsigned char* __restrict__ adj,
    const float* __restrict__ W1, const float* __restrict__ b1,
    const float* __restrict__ W2, const float* __restrict__ b2) {
    extern __shared__ float sm[];
    float* sW2    = sm;            // 64*136 tf32-rounded
    float* sR     = sm + 8704;     // 64*68  tf32-rounded
    float* s_hW1  = sm + 13056;
    float* sW1e   = sm + 13120;
    float* s_b2   = sm + 13312;
    float* s_h    = sm + 13440;
    float* s_redS = sm + 13568;
    float* s_part = s_redS;        // alias (disjoint lifetimes, synced)
    float* s_redMx= sm + 13824;
    float* s_redMn= sm + 14080;
    int*   s_jidx = (int*)(sm + 14336);
    int*   s_misc = s_jidx + 256;

    const int tid  = threadIdx.x;
    const int lane = tid & 31;
    const int warp = tid >> 5;
    const int gid  = lane >> 2;   // 0..7
    const int tg   = lane & 3;    // 0..3
    const int wm   = warp & 1;    // M-group (rows)
    const int wn   = warp >> 1;   // N-group (cols)

    // ---- Stage shared weights once per CTA ----
    for (int idx = tid; idx < E * D; idx += 256) {
        const int e = idx >> 7, d = idx & 127;
        sW2[e * 136 + d] = __uint_as_float(f2tf32(W2[idx]));
    }
    for (int idx = tid; idx < 3 * E; idx += 256) sW1e[idx] = W1[D * E + idx];
    if (tid < D) s_b2[tid] = b2[tid];

    for (int sub = 0; sub < 2; sub++) {
        const int bi = blockIdx.x * 2 + sub;
        __syncthreads();   // protects s_h/s_jidx/s_part reuse + weight staging

        if (tid < D) s_h[tid] = h[bi * D + tid];

        // Deterministic compaction of active j (ballot + scan)
        const bool m = adj[(size_t)bi * NN + tid] != 0;
        const unsigned bal = __ballot_sync(0xffffffffu, m);
        if (lane == 0) s_misc[warp] = __popc(bal);
        __syncthreads();
        int base = 0, cnt = 0;
#pragma unroll
        for (int w = 0; w < 8; w++) {
            const int c = s_misc[w];
            if (w < warp) base += c;
            cnt += c;
        }
        if (m) s_jidx[base + __popc(bal & ((1u << lane) - 1u))] = tid;

        // hW1 prologue (folded k1): 4-way K-split partial sums
        {
            const int e = tid & 63, q = tid >> 6;
            float acc = 0.f;
            const float* wp = W1 + (q * 32) * E + e;
            const float* hp = s_h + q * 32;
#pragma unroll 8
            for (int k = 0; k < 32; k++) acc += hp[k] * wp[k * E];
            s_part[q * 64 + e] = acc;
        }
        __syncthreads();
        if (tid < E)
            s_hW1[tid] = b1[tid] + s_part[tid] + s_part[64 + tid] +
                         s_part[128 + tid] + s_part[192 + tid];
        __syncthreads();

        float S[8], Mx[8], Mn[8];
#pragma unroll
        for (int i = 0; i < 8; i++) { S[i] = 0.f; Mx[i] = -1e30f; Mn[i] = 1e30f; }

        const int nTiles = (cnt + 63) >> 6;
        const int rrow = tid >> 2;          // 0..63 (R build row)
        const int re0  = (tid & 3) << 4;    // e-chunk base

        for (int t = 0; t < nTiles; t++) {
            if (t) __syncthreads();   // sR reuse across tiles
            // ---- Build R tile (64 rows x 64 e), tf32-rounded ----
            float f0 = 0.f, f1 = 0.f, f2v = 0.f;
            const int jg = t * 64 + rrow;
            if (jg < cnt) {
                const float* p = ef + ((size_t)bi * NN + s_jidx[jg]) * 3;
                f0 = p[0]; f1 = p[1]; f2v = p[2];
            }
#pragma unroll
            for (int i = 0; i < 16; i++) {
                const int e = re0 + i;
                float pre = s_hW1[e] + f0 * sW1e[e] + f1 * sW1e[64 + e] + f2v * sW1e[128 + e];
                pre = fmaxf(pre, 0.f);
                sR[rrow * 68 + e] = __uint_as_float(f2tf32(pre));
            }
            __syncthreads();

            // ---- 64x128 logits: warp = 32 rows x 32 cols, K=64 (8 x k8) ----
            float c[2][4][4];
#pragma unroll
            for (int mt = 0; mt < 2; mt++)
#pragma unroll
                for (int nt = 0; nt < 4; nt++)
#pragma unroll
                    for (int q = 0; q < 4; q++) c[mt][nt][q] = 0.f;

#pragma unroll
            for (int kc = 0; kc < 8; kc++) {
                const int k = kc * 8;
                uint32_t a[2][4], b[4][2];
#pragma unroll
                for (int mt = 0; mt < 2; mt++) {
                    const int row = wm * 32 + mt * 16 + gid;
                    const float* pr = sR + row * 68 + k + tg;
                    a[mt][0] = __float_as_uint(pr[0]);
                    a[mt][1] = __float_as_uint(pr[8 * 68]);
                    a[mt][2] = __float_as_uint(pr[4]);
                    a[mt][3] = __float_as_uint(pr[8 * 68 + 4]);
                }
#pragma unroll
                for (int nt = 0; nt < 4; nt++) {
                    const int col = wn * 32 + nt * 8 + gid;
                    const float* pb = sW2 + (k + tg) * 136 + col;
                    b[nt][0] = __float_as_uint(pb[0]);
                    b[nt][1] = __float_as_uint(pb[4 * 136]);
                }
#pragma unroll
                for (int mt = 0; mt < 2; mt++)
#pragma unroll
                    for (int nt = 0; nt < 4; nt++) {
                        asm("mma.sync.aligned.m16n8k8.row.col.f32.tf32.tf32.f32 "
                            "{%0,%1,%2,%3}, {%4,%5,%6,%7}, {%8,%9}, {%0,%1,%2,%3};\n"
                            : "+f"(c[mt][nt][0]), "+f"(c[mt][nt][1]),
                              "+f"(c[mt][nt][2]), "+f"(c[mt][nt][3])
                            : "r"(a[mt][0]), "r"(a[mt][1]), "r"(a[mt][2]), "r"(a[mt][3]),
                              "r"(b[nt][0]), "r"(b[nt][1]));
                    }
            }

            // ---- Epilogue: bias + sigmoid(tanh) + masked sum/max/min ----
#pragma unroll
            for (int mt = 0; mt < 2; mt++)
#pragma unroll
                for (int q = 0; q < 4; q++) {
                    const int rloc = wm * 32 + mt * 16 + gid + ((q >> 1) << 3);
                    const bool v = (t * 64 + rloc) < cnt;
#pragma unroll
                    for (int nt = 0; nt < 4; nt++) {
                        const int d = wn * 32 + nt * 8 + 2 * tg + (q & 1);
                        const float logit = c[mt][nt][q] + s_b2[d];
                        const float g = fmaf(0.5f, tanh_fast(0.5f * logit), 0.5f);
                        if (v) {
                            const int si = nt * 2 + (q & 1);
                            S[si] += g;
                            Mx[si] = fmaxf(Mx[si], g);
                            Mn[si] = fminf(Mn[si], g);
                        }
                    }
                }
        }

        // ---- Reduce across the 8 lanes sharing each d ----
#pragma unroll
        for (int i = 0; i < 8; i++) {
#pragma unroll
            for (int off = 4; off < 32; off <<= 1) {
                S[i]  += __shfl_xor_sync(0xffffffffu, S[i], off);
                Mx[i]  = fmaxf(Mx[i], __shfl_xor_sync(0xffffffffu, Mx[i], off));
                Mn[i]  = fminf(Mn[i], __shfl_xor_sync(0xffffffffu, Mn[i], off));
            }
        }
        __syncthreads();   // s_redS aliases s_part
        if (lane < 4) {
#pragma unroll
            for (int nt = 0; nt < 4; nt++)
#pragma unroll
                for (int q = 0; q < 2; q++) {
                    const int d = wn * 32 + nt * 8 + 2 * lane + q;
                    const int si = nt * 2 + q;
                    s_redS [wm * 128 + d] = S[si];
                    s_redMx[wm * 128 + d] = Mx[si];
                    s_redMn[wm * 128 + d] = Mn[si];
                }
        }
        __syncthreads();
        if (tid < D) {
            const float St  = s_redS[tid]  + s_redS[128 + tid];
            const float Mxt = fmaxf(s_redMx[tid], s_redMx[128 + tid]);
            const float Mnt = fminf(s_redMn[tid], s_redMn[128 + tid]);
            const float hv  = s_h[tid];
            const float cl  = (cnt > 0) ? (float)cnt : 1.f;
            g_aggmean[bi * D + tid] = St * hv / cl;
            float amax = 0.f;
            if (cnt > 0) amax = (hv >= 0.f) ? hv * Mxt : hv * Mnt;
            g_aggmax[bi * D + tid] = amax;
        }
    }
}

// ---------------------------------------------------------------------------
// K3: upd = relu([h, agg_mean, agg_max] @ U1 + b3) @ U2 + b4
//     out = LayerNorm(h + upd) * gamma + beta
// TR=8 rows/CTA, grid=256 (covers all SMs), transposed SMEM staging so each
// k-step is: 1 coalesced LDG (weight col) + 1 broadcast LDS.128 (4 rows) + 4 FMA.
// ---------------------------------------------------------------------------
#define TR 8
__global__ void __launch_bounds__(256) k3_upd(
    const float* __restrict__ h,
    const float* __restrict__ U1, const float* __restrict__ b3,
    const float* __restrict__ U2, const float* __restrict__ b4,
    const float* __restrict__ gamma, const float* __restrict__ beta,
    float* __restrict__ out) {
    __shared__ __align__(16) float s_inT[384][12];   // [k][row], pad 12 (16B-aligned groups)
    __shared__ __align__(16) float s_midT[128][12];  // [k][row]
    __shared__ float s_x[TR][129];
    const int tid = threadIdx.x;
    const int r0 = blockIdx.x * TR;

    // Transposed staging: each thread handles one (row, 4k-chunk) per source.
    {
        const int r = tid >> 5, c = tid & 31;   // r 0..7, c 0..31
        const int k = c * 4;
        const float4 va = ((const float4*)(h + (size_t)(r0 + r) * D))[c];
        const float4 vb = ((const float4*)(g_aggmean + (size_t)(r0 + r) * D))[c];
        const float4 vc = ((const float4*)(g_aggmax + (size_t)(r0 + r) * D))[c];
        s_inT[k + 0][r] = va.x; s_inT[k + 1][r] = va.y;
        s_inT[k + 2][r] = va.z; s_inT[k + 3][r] = va.w;
        s_inT[128 + k + 0][r] = vb.x; s_inT[128 + k + 1][r] = vb.y;
        s_inT[128 + k + 2][r] = vb.z; s_inT[128 + k + 3][r] = vb.w;
        s_inT[256 + k + 0][r] = vc.x; s_inT[256 + k + 1][r] = vc.y;
        s_inT[256 + k + 2][r] = vc.z; s_inT[256 + k + 3][r] = vc.w;
    }
    __syncthreads();

    const int e  = tid & 127;       // output column
    const int rg = tid >> 7;        // row group: rows rg*4 .. rg*4+3
    float a0 = 0.f, a1 = 0.f, a2 = 0.f, a3 = 0.f;

    for (int k = 0; k < 384; k += 4) {
        const float w0 = __ldg(U1 + (k + 0) * D + e);
        const float w1 = __ldg(U1 + (k + 1) * D + e);
        const float w2 = __ldg(U1 + (k + 2) * D + e);
        const float w3 = __ldg(U1 + (k + 3) * D + e);
        const float4 v0 = *(const float4*)&s_inT[k + 0][rg * 4];
        const float4 v1 = *(const float4*)&s_inT[k + 1][rg * 4];
        const float4 v2 = *(const float4*)&s_inT[k + 2][rg * 4];
        const float4 v3 = *(const float4*)&s_inT[k + 3][rg * 4];
        a0 += v0.x * w0 + v1.x * w1 + v2.x * w2 + v3.x * w3;
        a1 += v0.y * w0 + v1.y * w1 + v2.y * w2 + v3.y * w3;
        a2 += v0.z * w0 + v1.z * w1 + v2.z * w2 + v3.z * w3;
        a3 += v0.w * w0 + v1.w * w1 + v2.w * w2 + v3.w * w3;
    }
    {
        const float bb = b3[e];
        float4 mv;
        mv.x = fmaxf(a0 + bb, 0.f); mv.y = fmaxf(a1 + bb, 0.f);
        mv.z = fmaxf(a2 + bb, 0.f); mv.w = fmaxf(a3 + bb, 0.f);
        *(float4*)&s_midT[e][rg * 4] = mv;
    }
    __syncthreads();

    a0 = a1 = a2 = a3 = 0.f;
    for (int k = 0; k < 128; k += 4) {
        const float w0 = __ldg(U2 + (k + 0) * D + e);
        const float w1 = __ldg(U2 + (k + 1) * D + e);
        const float w2 = __ldg(U2 + (k + 2) * D + e);
        const float w3 = __ldg(U2 + (k + 3) * D + e);
        const float4 v0 = *(const float4*)&s_midT[k + 0][rg * 4];
        const float4 v1 = *(const float4*)&s_midT[k + 1][rg * 4];
        const float4 v2 = *(const float4*)&s_midT[k + 2][rg * 4];
        const float4 v3 = *(const float4*)&s_midT[k + 3][rg * 4];
        a0 += v0.x * w0 + v1.x * w1 + v2.x * w2 + v3.x * w3;
        a1 += v0.y * w0 + v1.y * w1 + v2.y * w2 + v3.y * w3;
        a2 += v0.z * w0 + v1.z * w1 + v2.z * w2 + v3.z * w3;
        a3 += v0.w * w0 + v1.w * w1 + v2.w * w2 + v3.w * w3;
    }
    {
        const float b4v = b4[e];
        // h[row][e] lives at s_inT[e][row] (e < 128 is the h segment)
        s_x[rg * 4 + 0][e] = s_inT[e][rg * 4 + 0] + a0 + b4v;
        s_x[rg * 4 + 1][e] = s_inT[e][rg * 4 + 1] + a1 + b4v;
        s_x[rg * 4 + 2][e] = s_inT[e][rg * 4 + 2] + a2 + b4v;
        s_x[rg * 4 + 3][e] = s_inT[e][rg * 4 + 3] + a3 + b4v;
    }
    __syncthreads();

    // LayerNorm: 8 warps, one row each
    const int warp = tid >> 5, lane = tid & 31;
    float s = 0.f, s2 = 0.f, v[4];
#pragma unroll
    for (int i = 0; i < 4; i++) {
        v[i] = s_x[warp][lane + i * 32];
        s += v[i]; s2 += v[i] * v[i];
    }
#pragma unroll
    for (int off = 1; off < 32; off <<= 1) {
        s  += __shfl_xor_sync(0xffffffffu, s, off);
        s2 += __shfl_xor_sync(0xffffffffu, s2, off);
    }
    const float mu  = s * (1.f / 128.f);
    const float var = s2 * (1.f / 128.f) - mu * mu;
    const float inv = rsqrtf(var + 1e-5f);
#pragma unroll
    for (int i = 0; i < 4; i++) {
        const int d = lane + i * 32;
        out[(size_t)(r0 + warp) * D + d] = (v[i] - mu) * inv * gamma[d] + beta[d];
    }
}

// ---------------------------------------------------------------------------
extern "C" void kernel_launch(void* const* d_in, const int* in_sizes, int n_in,
                              void* d_out, int out_size) {
    const float* h    = (const float*)d_in[0];
    const float* ef   = (const float*)d_in[1];
    const unsigned char* adj = (const unsigned char*)d_in[2];
    const float* W1   = (const float*)d_in[3];
    const float* b1   = (const float*)d_in[4];
    const float* W2   = (const float*)d_in[5];
    const float* b2   = (const float*)d_in[6];
    const float* U1   = (const float*)d_in[7];
    const float* b3   = (const float*)d_in[8];
    const float* U2   = (const float*)d_in[9];
    const float* b4   = (const float*)d_in[10];
    const float* gamma= (const float*)d_in[11];
    const float* beta = (const float*)d_in[12];
    float* out = (float*)d_out;

    cudaFuncSetAttribute(k2_main, cudaFuncAttributeMaxDynamicSharedMemorySize,
                         K2_SMEM_BYTES);

    k2_main<<<BN / 2, 256, K2_SMEM_BYTES>>>(h, ef, adj, W1, b1, W2, b2);
    k3_upd<<<BN / TR, 256>>>(h, U1, b3, U2, b4, gamma, beta, out);
}